// round 10
// baseline (speedup 1.0000x reference)
#include <cuda_runtime.h>
#include <stdint.h>
#include <math.h>
#include <float.h>

// Shapes (fixed): MSA_emb (1,512,768,256) f32; seq_mask (1,512) i32;
// Wq,Wk (256,256) f32; out (1,512,768,8,1) f32
#define R_DIM 512
#define C_DIM 768
#define H_DIM 8
static constexpr float SCALE = 0.17677669529663687f; // 1/sqrt(32)

typedef unsigned long long u64;

// P[c][e][h] (h-major: 8 head coeffs = one 32B chunk)
__device__ float g_P[C_DIM * 2048];

// ---- packed f32x2 helpers (b64 regs) ----
__device__ __forceinline__ u64 ffma2(u64 a, u64 b, u64 c) {
    u64 d;
    asm("fma.rn.f32x2 %0, %1, %2, %3;" : "=l"(d) : "l"(a), "l"(b), "l"(c));
    return d;
}
__device__ __forceinline__ u64 padd2(u64 a, u64 b) {
    u64 d;
    asm("add.rn.f32x2 %0, %1, %2;" : "=l"(d) : "l"(a), "l"(b));
    return d;
}
__device__ __forceinline__ u64 pack2(float x, float y) {
    u64 d; asm("mov.b64 %0, {%1, %2};" : "=l"(d) : "f"(x), "f"(y)); return d;
}
__device__ __forceinline__ void unpack2(u64 d, float& x, float& y) {
    asm("mov.b64 {%0, %1}, %2;" : "=f"(x), "=f"(y) : "l"(d));
}
__device__ __forceinline__ void cpasync16(unsigned int dst, const void* src) {
    asm volatile("cp.async.cg.shared.global [%0], [%1], 16;\n" :: "r"(dst), "l"(src));
}

// ---------------------------------------------------------------------------
// kQP: Q = SCALE*(msa0 @ Wq^T); P[c][e][h] = sum_d Q[c][h*32+d]*Wk[h*32+d][e]
// grid 256 (3 c per block), 256 threads.
// ---------------------------------------------------------------------------
__global__ void __launch_bounds__(256) kQP(const float* __restrict__ msa,
                                           const float* __restrict__ wq,
                                           const float* __restrict__ wk) {
    extern __shared__ float smq[];
    float* xs   = smq;             // [3][256]
    float* qs   = xs + 3 * 256;    // [3][256]
    float* ws   = qs + 3 * 256;    // [32][256] (one head slice of Wk)
    float* pbuf = ws + 8192;       // [3][2048]
    const int c0  = blockIdx.x * 3;
    const int tid = threadIdx.x;

    for (int i = tid; i < 3 * 64; i += 256) {
        int cc = i >> 6, f4 = i & 63;
        reinterpret_cast<float4*>(&xs[cc * 256 + f4 * 4])[0] =
            reinterpret_cast<const float4*>(msa + (size_t)(c0 + cc) * 256)[f4];
    }
    __syncthreads();

    {   // Q: thread = output o = tid
        float acc[3] = {0, 0, 0};
        const float4* wrow = reinterpret_cast<const float4*>(wq + (size_t)tid * 256);
#pragma unroll 8
        for (int f4 = 0; f4 < 64; f4++) {
            float4 w = __ldg(&wrow[f4]);
#pragma unroll
            for (int cc = 0; cc < 3; cc++) {
                const float* x = &xs[cc * 256 + f4 * 4];
                acc[cc] += w.x * x[0] + w.y * x[1] + w.z * x[2] + w.w * x[3];
            }
        }
#pragma unroll
        for (int cc = 0; cc < 3; cc++) qs[cc * 256 + tid] = acc[cc] * SCALE;
    }

    // P stage: per-head Wk slice via smem; next slice prefetched into regs
    const float4* wk4 = reinterpret_cast<const float4*>(wk);
    float4* ws4 = reinterpret_cast<float4*>(ws);
    float4 r[8];
#pragma unroll
    for (int i = 0; i < 8; i++) r[i] = __ldg(&wk4[tid + i * 256]);  // h=0 slice

    for (int h = 0; h < 8; h++) {
        __syncthreads();   // previous slice fully consumed (covers qs on h=0)
#pragma unroll
        for (int i = 0; i < 8; i++) ws4[tid + i * 256] = r[i];
        __syncthreads();
        if (h < 7) {
#pragma unroll
            for (int i = 0; i < 8; i++)
                r[i] = __ldg(&wk4[(h + 1) * 2048 + tid + i * 256]);
        }
        float w[32];
#pragma unroll
        for (int d = 0; d < 32; d++) w[d] = ws[d * 256 + tid];
#pragma unroll
        for (int cc = 0; cc < 3; cc++) {
            const float4* q4 = reinterpret_cast<const float4*>(qs + cc * 256 + h * 32);
            float a = 0.f;
#pragma unroll
            for (int j = 0; j < 8; j++) {
                float4 qv = q4[j];
                a += qv.x * w[4 * j] + qv.y * w[4 * j + 1] +
                     qv.z * w[4 * j + 2] + qv.w * w[4 * j + 3];
            }
            pbuf[cc * 2048 + tid * 8 + h] = a;
        }
    }
    __syncthreads();

    float4* gp = reinterpret_cast<float4*>(g_P + (size_t)c0 * 2048);
    const float4* pb = reinterpret_cast<const float4*>(pbuf);
    for (int i = tid; i < 1536; i += 256) gp[i] = pb[i];
}

// ---------------------------------------------------------------------------
// kMain: block per c. 32 tiles x 16 rows, 4-buffer cp.async pipeline with
// prefetch issued BEFORE compute (3 tiles in flight). Thread = (row = tid&15,
// e-group = tid>>4, 16 e each). Packed f32x2 over head pairs; conflict-free
// partial combine; masked softmax; transposed write.
// 768 blocks, 256 threads, smem ~103.8 KB (2 blocks/SM).
// ---------------------------------------------------------------------------
static constexpr int XS_STRIDE = 260;          // 1040B row stride, conflict-free
static constexpr int TILE_F = 16 * XS_STRIDE;  // 4160 floats per buffer
static constexpr int QKS = 516;
static constexpr int PART_S = 66;              // u64 stride per e-group (16 rows x 4 pairs + 2 pad)

__global__ void __launch_bounds__(256) kMain(const float* __restrict__ msa,
                                             const int* __restrict__ mask,
                                             float* __restrict__ out) {
    extern __shared__ float sm[];
    float* xs   = sm;                           // 4 * 4160 = 16640
    float* ps   = sm + 4 * TILE_F;              // 2048
    float* qk   = ps + 2048;                    // 8*516 = 4128
    u64*   part = (u64*)(qk + 8 * QKS);         // 16 * 66 u64 = 8448 B (16B aligned)
    int*   msk  = (int*)(part + 16 * PART_S);   // 512
    float* sinv = (float*)(msk + 512);          // 8

    const int c    = blockIdx.x;
    const int tid  = threadIdx.x;
    const int lane = tid & 31;
    const int row  = tid & 15;   // row within 16-row tile
    const int eg   = tid >> 4;   // e-group (16 e each), warp-spans 2 groups

    const unsigned int xs_s = (unsigned int)__cvta_generic_to_shared(xs);

    // prefetch tiles 0,1,2
#pragma unroll
    for (int t = 0; t < 3; t++) {
#pragma unroll
        for (int k = 0; k < 4; k++) {
            int i = tid + k * 256;           // 0..1023
            int r = i >> 6, col = i & 63;
            cpasync16(xs_s + (unsigned int)((t * TILE_F + r * XS_STRIDE + col * 4) * 4),
                      msa + ((size_t)(t * 16 + r) * C_DIM + c) * 256 + col * 4);
        }
        asm volatile("cp.async.commit_group;");
    }
    {   // P slice + mask (overlaps with prefetch)
        float4* p4 = reinterpret_cast<float4*>(ps);
        const float4* g4 = reinterpret_cast<const float4*>(g_P + (size_t)c * 2048);
        for (int i = tid; i < 512; i += 256) p4[i] = g4[i];
        for (int i = tid; i < 512; i += 256) msk[i] = mask[i];
    }

    const ulonglong2* pd = reinterpret_cast<const ulonglong2*>(ps);

    for (int t = 0; t < 32; t++) {
        if (t < 30)      asm volatile("cp.async.wait_group 2;");
        else if (t == 30) asm volatile("cp.async.wait_group 1;");
        else              asm volatile("cp.async.wait_group 0;");
        __syncthreads();   // tile t visible to all; buf (t+3)&3 free (consumed in t-1)

        // prefetch tile t+3 FIRST (keeps 3 tiles in flight during compute)
        if (t < 29) {
            int tn = t + 3;
#pragma unroll
            for (int k = 0; k < 4; k++) {
                int i = tid + k * 256;
                int r = i >> 6, col = i & 63;
                cpasync16(xs_s + (unsigned int)(((tn & 3) * TILE_F + r * XS_STRIDE + col * 4) * 4),
                          msa + ((size_t)(tn * 16 + r) * C_DIM + c) * 256 + col * 4);
            }
            asm volatile("cp.async.commit_group;");
        }

        // partial QK for (row, e in [eg*16, eg*16+16))
        const float* xrow = xs + (t & 3) * TILE_F + row * XS_STRIDE + eg * 16;
        const float4* x4 = reinterpret_cast<const float4*>(xrow);
        u64 a0 = 0, a1 = 0, a2 = 0, a3 = 0;   // (+0.0f,+0.0f) pairs
#pragma unroll
        for (int i = 0; i < 4; i++) {
            float4 xv = x4[i];
            int e0 = eg * 16 + i * 4;
            {
                ulonglong2 pA = pd[e0 * 2], pB = pd[e0 * 2 + 1];
                u64 dx = pack2(xv.x, xv.x);
                a0 = ffma2(pA.x, dx, a0); a1 = ffma2(pA.y, dx, a1);
                a2 = ffma2(pB.x, dx, a2); a3 = ffma2(pB.y, dx, a3);
            }
            {
                ulonglong2 pA = pd[(e0 + 1) * 2], pB = pd[(e0 + 1) * 2 + 1];
                u64 dx = pack2(xv.y, xv.y);
                a0 = ffma2(pA.x, dx, a0); a1 = ffma2(pA.y, dx, a1);
                a2 = ffma2(pB.x, dx, a2); a3 = ffma2(pB.y, dx, a3);
            }
            {
                ulonglong2 pA = pd[(e0 + 2) * 2], pB = pd[(e0 + 2) * 2 + 1];
                u64 dx = pack2(xv.z, xv.z);
                a0 = ffma2(pA.x, dx, a0); a1 = ffma2(pA.y, dx, a1);
                a2 = ffma2(pB.x, dx, a2); a3 = ffma2(pB.y, dx, a3);
            }
            {
                ulonglong2 pA = pd[(e0 + 3) * 2], pB = pd[(e0 + 3) * 2 + 1];
                u64 dx = pack2(xv.w, xv.w);
                a0 = ffma2(pA.x, dx, a0); a1 = ffma2(pA.y, dx, a1);
                a2 = ffma2(pB.x, dx, a2); a3 = ffma2(pB.y, dx, a3);
            }
        }
        // part[eg][row][pair]: contiguous STS.128 pairs, conflict-free
        u64* pw = part + eg * PART_S + row * 4;
        pw[0] = a0; pw[1] = a1; pw[2] = a2; pw[3] = a3;
        __syncthreads();

        // combine 16 e-group partials -> qk (64 threads: row x pair)
        if (tid < 64) {
            int rr = tid >> 2, p = tid & 3;
            const u64* pr = part + rr * 4 + p;
            u64 s = pr[0];
#pragma unroll
            for (int g = 1; g < 16; g++) s = padd2(s, pr[g * PART_S]);
            float v0, v1;
            unpack2(s, v0, v1);
            int R = t * 16 + rr;
            qk[(2 * p) * QKS + R]     = v0;
            qk[(2 * p + 1) * QKS + R] = v1;
        }
    }
    __syncthreads();

    // masked softmax over r: warp h handles head h
    {
        int h = tid >> 5;
        float vals[16];
        float mx = -FLT_MAX;
#pragma unroll
        for (int j = 0; j < 16; j++) {
            int r = lane + 32 * j;
            float v = (msk[r] != 0) ? qk[h * QKS + r] : -FLT_MAX;
            vals[j] = v;
            mx = fmaxf(mx, v);
        }
#pragma unroll
        for (int s = 16; s; s >>= 1) mx = fmaxf(mx, __shfl_xor_sync(0xffffffffu, mx, s));
        float sum = 0.f;
#pragma unroll
        for (int j = 0; j < 16; j++) {
            int r = lane + 32 * j;
            float e = (msk[r] != 0) ? __expf(vals[j] - mx) : 0.f;
            sum += e;
            qk[h * QKS + r] = e;
        }
#pragma unroll
        for (int s = 16; s; s >>= 1) sum += __shfl_xor_sync(0xffffffffu, sum, s);
        if (lane == 0) sinv[h] = 1.f / sum;
    }
    __syncthreads();

    // transposed write: out[r*6144 + c*8 + h] (32B contiguous per r)
#pragma unroll
    for (int k = 0; k < 16; k++) {
        int idx = tid + 256 * k;          // 512 r x 8 h
        int r = idx >> 3, h = idx & 7;
        out[(size_t)r * (C_DIM * H_DIM) + c * H_DIM + h] =
            qk[h * QKS + r] * sinv[h];
    }
}

// ---------------------------------------------------------------------------
extern "C" void kernel_launch(void* const* d_in, const int* in_sizes, int n_in,
                              void* d_out, int out_size) {
    const float* msa  = (const float*)d_in[0];
    const int*   mask = (const int*)d_in[1];
    const float* wq   = (const float*)d_in[2];
    const float* wk   = (const float*)d_in[3];
    float* out = (float*)d_out;

    const int smemQP = (3 * 256 + 3 * 256 + 8192 + 3 * 2048) * 4;  // 63,488
    const int smemMain = (4 * TILE_F + 2048 + 8 * QKS) * 4         // xs+ps+qk
                         + 16 * PART_S * 8                          // part
                         + 512 * 4 + 8 * 4;                        // msk+sinv  = 106,272
    cudaFuncSetAttribute(kQP,   cudaFuncAttributeMaxDynamicSharedMemorySize, smemQP);
    cudaFuncSetAttribute(kMain, cudaFuncAttributeMaxDynamicSharedMemorySize, smemMain);

    kQP<<<256, 256, smemQP>>>(msa, wq, wk);
    kMain<<<768, 256, smemMain>>>(msa, mask, out);
}

// round 12
// speedup vs baseline: 1.0658x; 1.0658x over previous
#include <cuda_runtime.h>
#include <stdint.h>
#include <math.h>
#include <float.h>

// Shapes (fixed): MSA_emb (1,512,768,256) f32; seq_mask (1,512) i32;
// Wq,Wk (256,256) f32; out (1,512,768,8,1) f32
#define R_DIM 512
#define C_DIM 768
#define H_DIM 8
static constexpr float SCALE = 0.17677669529663687f; // 1/sqrt(32)

typedef unsigned long long u64;

// P[c][e][h] (h-major: 8 head coeffs = one 32B chunk)
__device__ float g_P[C_DIM * 2048];

// ---- packed f32x2 helpers (b64 regs) ----
__device__ __forceinline__ u64 ffma2(u64 a, u64 b, u64 c) {
    u64 d;
    asm("fma.rn.f32x2 %0, %1, %2, %3;" : "=l"(d) : "l"(a), "l"(b), "l"(c));
    return d;
}
__device__ __forceinline__ u64 padd2(u64 a, u64 b) {
    u64 d;
    asm("add.rn.f32x2 %0, %1, %2;" : "=l"(d) : "l"(a), "l"(b));
    return d;
}
__device__ __forceinline__ u64 pack2(float x, float y) {
    u64 d; asm("mov.b64 %0, {%1, %2};" : "=l"(d) : "f"(x), "f"(y)); return d;
}
__device__ __forceinline__ void unpack2(u64 d, float& x, float& y) {
    asm("mov.b64 {%0, %1}, %2;" : "=f"(x), "=f"(y) : "l"(d));
}
__device__ __forceinline__ void cpasync16(unsigned int dst, const void* src) {
    asm volatile("cp.async.cg.shared.global [%0], [%1], 16;\n" :: "r"(dst), "l"(src));
}

// ---------------------------------------------------------------------------
// kQP: Q = SCALE*(msa0 @ Wq^T); P[c][e][h] = sum_d Q[c][h*32+d]*Wk[h*32+d][e]
// grid 256 (3 c per block), 256 threads. (unchanged — known good)
// ---------------------------------------------------------------------------
__global__ void __launch_bounds__(256) kQP(const float* __restrict__ msa,
                                           const float* __restrict__ wq,
                                           const float* __restrict__ wk) {
    extern __shared__ float smq[];
    float* xs   = smq;             // [3][256]
    float* qs   = xs + 3 * 256;    // [3][256]
    float* ws   = qs + 3 * 256;    // [32][256] (one head slice of Wk)
    float* pbuf = ws + 8192;       // [3][2048]
    const int c0  = blockIdx.x * 3;
    const int tid = threadIdx.x;

    for (int i = tid; i < 3 * 64; i += 256) {
        int cc = i >> 6, f4 = i & 63;
        reinterpret_cast<float4*>(&xs[cc * 256 + f4 * 4])[0] =
            reinterpret_cast<const float4*>(msa + (size_t)(c0 + cc) * 256)[f4];
    }
    __syncthreads();

    {   // Q: thread = output o = tid
        float acc[3] = {0, 0, 0};
        const float4* wrow = reinterpret_cast<const float4*>(wq + (size_t)tid * 256);
#pragma unroll 8
        for (int f4 = 0; f4 < 64; f4++) {
            float4 w = __ldg(&wrow[f4]);
#pragma unroll
            for (int cc = 0; cc < 3; cc++) {
                const float* x = &xs[cc * 256 + f4 * 4];
                acc[cc] += w.x * x[0] + w.y * x[1] + w.z * x[2] + w.w * x[3];
            }
        }
#pragma unroll
        for (int cc = 0; cc < 3; cc++) qs[cc * 256 + tid] = acc[cc] * SCALE;
    }

    // P stage: per-head Wk slice via smem; next slice prefetched into regs
    const float4* wk4 = reinterpret_cast<const float4*>(wk);
    float4* ws4 = reinterpret_cast<float4*>(ws);
    float4 r[8];
#pragma unroll
    for (int i = 0; i < 8; i++) r[i] = __ldg(&wk4[tid + i * 256]);  // h=0 slice

    for (int h = 0; h < 8; h++) {
        __syncthreads();
#pragma unroll
        for (int i = 0; i < 8; i++) ws4[tid + i * 256] = r[i];
        __syncthreads();
        if (h < 7) {
#pragma unroll
            for (int i = 0; i < 8; i++)
                r[i] = __ldg(&wk4[(h + 1) * 2048 + tid + i * 256]);
        }
        float w[32];
#pragma unroll
        for (int d = 0; d < 32; d++) w[d] = ws[d * 256 + tid];
#pragma unroll
        for (int cc = 0; cc < 3; cc++) {
            const float4* q4 = reinterpret_cast<const float4*>(qs + cc * 256 + h * 32);
            float a = 0.f;
#pragma unroll
            for (int j = 0; j < 8; j++) {
                float4 qv = q4[j];
                a += qv.x * w[4 * j] + qv.y * w[4 * j + 1] +
                     qv.z * w[4 * j + 2] + qv.w * w[4 * j + 3];
            }
            pbuf[cc * 2048 + tid * 8 + h] = a;
        }
    }
    __syncthreads();

    float4* gp = reinterpret_cast<float4*>(g_P + (size_t)c0 * 2048);
    const float4* pb = reinterpret_cast<const float4*>(pbuf);
    for (int i = tid; i < 1536; i += 256) gp[i] = pb[i];
}

// ---------------------------------------------------------------------------
// kMain: block per c. 32 tiles x 16 rows, 3-buffer cp.async pipeline,
// ONE __syncthreads per tile (combine deferred one tile, part double-buffered).
// Thread = (hp = tid&1, eg = (tid>>1)&7, rsub = (tid>>4)&1, q = (tid>>5)&3,
//           rg = tid>>7): owns e in [q*64+eg*8, +8) x 4 heads, rows rowbase..+3.
// P slice (8 ulonglong2) in REGISTERS for the whole kernel; eg-partials
// reduced by warp shfl_xor; only a 4-way (q) smem combine remains.
// 768 blocks, 256 threads, smem 72,608 B -> 3 blocks/SM.
// ---------------------------------------------------------------------------
static constexpr int XS_STRIDE = 260;          // 1040B row stride
static constexpr int TILE_F = 16 * XS_STRIDE;  // 4160 floats per buffer
static constexpr int QKS = 516;

__global__ void __launch_bounds__(256, 3) kMain(const float* __restrict__ msa,
                                                const int* __restrict__ mask,
                                                float* __restrict__ out) {
    extern __shared__ float sm[];
    float* xs   = sm;                      // 3 * 4160 = 12480
    float* qk   = xs + 3 * TILE_F;         // 8*516 = 4128
    u64*   part = (u64*)(qk + 8 * QKS);    // 2 buffers x 256 u64 (= 1024 floats)
    int*   msk  = (int*)(part + 512);      // 512
    float* sinv = (float*)(msk + 512);     // 8

    const int c    = blockIdx.x;
    const int tid  = threadIdx.x;
    const int lane = tid & 31;
    const int hp   = tid & 1;          // head half: h0-3 or h4-7
    const int eg   = (tid >> 1) & 7;   // e-oct within quarter
    const int rsub = (tid >> 4) & 1;
    const int q    = (tid >> 5) & 3;   // e-quarter
    const int rg   = tid >> 7;
    const int rowbase = rg * 8 + rsub * 4;      // rows rowbase..rowbase+3
    const int ebase   = q * 64 + eg * 8;

    const unsigned int xs_s = (unsigned int)__cvta_generic_to_shared(xs);

    // prefetch tiles 0,1
#pragma unroll
    for (int t = 0; t < 2; t++) {
#pragma unroll
        for (int k = 0; k < 4; k++) {
            int i = tid + k * 256;           // 0..1023
            int r = i >> 6, col = i & 63;
            cpasync16(xs_s + (unsigned int)((t * TILE_F + r * XS_STRIDE + col * 4) * 4),
                      msa + ((size_t)(t * 16 + r) * C_DIM + c) * 256 + col * 4);
        }
        asm volatile("cp.async.commit_group;");
    }
    for (int i = tid; i < 512; i += 256) msk[i] = mask[i];

    // ---- P slice into registers (once, straight from L2) ----
    const ulonglong2* gp = reinterpret_cast<const ulonglong2*>(g_P + (size_t)c * 2048);
    ulonglong2 Pr[8];
#pragma unroll
    for (int i = 0; i < 8; i++) Pr[i] = __ldg(&gp[(ebase + i) * 2 + hp]);

    for (int t = 0; t < 32; t++) {
        if (t < 31) asm volatile("cp.async.wait_group 1;");
        else        asm volatile("cp.async.wait_group 0;");
        __syncthreads();   // tile t visible to all; part[(t-1)&1] STS visible

        // prefetch tile t+2 into buffer (t+2)%3 (consumed at t-1)
        if (t < 30) {
            int tn = t + 2;
#pragma unroll
            for (int k = 0; k < 4; k++) {
                int i = tid + k * 256;
                int r = i >> 6, col = i & 63;
                cpasync16(xs_s + (unsigned int)(((tn % 3) * TILE_F + r * XS_STRIDE + col * 4) * 4),
                          msa + ((size_t)(tn * 16 + r) * C_DIM + c) * 256 + col * 4);
            }
            asm volatile("cp.async.commit_group;");
        }

        // ---- compute 4 rows x 8 e x 4 heads, all P from registers ----
        const float* xb = xs + (t % 3) * TILE_F;
        u64 acc[4][2];
#pragma unroll
        for (int k = 0; k < 4; k++) { acc[k][0] = 0; acc[k][1] = 0; }
#pragma unroll
        for (int k = 0; k < 4; k++) {
            const float4* x4 = reinterpret_cast<const float4*>(
                xb + (rowbase + k) * XS_STRIDE + ebase);
            float4 xa = x4[0], xc = x4[1];
            u64 dx;
            dx = pack2(xa.x, xa.x); acc[k][0] = ffma2(Pr[0].x, dx, acc[k][0]); acc[k][1] = ffma2(Pr[0].y, dx, acc[k][1]);
            dx = pack2(xa.y, xa.y); acc[k][0] = ffma2(Pr[1].x, dx, acc[k][0]); acc[k][1] = ffma2(Pr[1].y, dx, acc[k][1]);
            dx = pack2(xa.z, xa.z); acc[k][0] = ffma2(Pr[2].x, dx, acc[k][0]); acc[k][1] = ffma2(Pr[2].y, dx, acc[k][1]);
            dx = pack2(xa.w, xa.w); acc[k][0] = ffma2(Pr[3].x, dx, acc[k][0]); acc[k][1] = ffma2(Pr[3].y, dx, acc[k][1]);
            dx = pack2(xc.x, xc.x); acc[k][0] = ffma2(Pr[4].x, dx, acc[k][0]); acc[k][1] = ffma2(Pr[4].y, dx, acc[k][1]);
            dx = pack2(xc.y, xc.y); acc[k][0] = ffma2(Pr[5].x, dx, acc[k][0]); acc[k][1] = ffma2(Pr[5].y, dx, acc[k][1]);
            dx = pack2(xc.z, xc.z); acc[k][0] = ffma2(Pr[6].x, dx, acc[k][0]); acc[k][1] = ffma2(Pr[6].y, dx, acc[k][1]);
            dx = pack2(xc.w, xc.w); acc[k][0] = ffma2(Pr[7].x, dx, acc[k][0]); acc[k][1] = ffma2(Pr[7].y, dx, acc[k][1]);
        }

        // ---- reduce across eg (lane bits 1..3) via shfl_xor ----
#pragma unroll
        for (int off = 2; off <= 8; off <<= 1) {
#pragma unroll
            for (int k = 0; k < 4; k++) {
                acc[k][0] = padd2(acc[k][0], __shfl_xor_sync(0xffffffffu, acc[k][0], off));
                acc[k][1] = padd2(acc[k][1], __shfl_xor_sync(0xffffffffu, acc[k][1], off));
            }
        }

        // eg==0 lanes hold (q,hp,row) block sums -> part[t&1]
        if (eg == 0) {
            u64* pb = part + (t & 1) * 256;
#pragma unroll
            for (int k = 0; k < 4; k++) {
                u64* w = pb + (rowbase + k) * 16 + q * 4 + hp * 2;
                w[0] = acc[k][0]; w[1] = acc[k][1];
            }
        }

        // ---- combine tile t-1 (4-way over q) ----
        if (t > 0 && tid < 64) {
            int rr = tid >> 2, p = tid & 3;   // p = hp*2 + a  -> heads (2p, 2p+1)
            const u64* pr = part + ((t - 1) & 1) * 256 + rr * 16 + p;
            u64 s = padd2(padd2(pr[0], pr[4]), padd2(pr[8], pr[12]));
            float v0, v1;
            unpack2(s, v0, v1);
            int R = (t - 1) * 16 + rr;
            qk[(2 * p) * QKS + R]     = v0;
            qk[(2 * p + 1) * QKS + R] = v1;
        }
    }
    __syncthreads();
    if (tid < 64) {   // combine last tile (31)
        int rr = tid >> 2, p = tid & 3;
        const u64* pr = part + (31 & 1) * 256 + rr * 16 + p;
        u64 s = padd2(padd2(pr[0], pr[4]), padd2(pr[8], pr[12]));
        float v0, v1;
        unpack2(s, v0, v1);
        int R = 31 * 16 + rr;
        qk[(2 * p) * QKS + R]     = v0;
        qk[(2 * p + 1) * QKS + R] = v1;
    }
    __syncthreads();

    // masked softmax over r: warp h handles head h
    {
        int h = tid >> 5;
        float vals[16];
        float mx = -FLT_MAX;
#pragma unroll
        for (int j = 0; j < 16; j++) {
            int r = lane + 32 * j;
            float v = (msk[r] != 0) ? qk[h * QKS + r] : -FLT_MAX;
            vals[j] = v;
            mx = fmaxf(mx, v);
        }
#pragma unroll
        for (int s = 16; s; s >>= 1) mx = fmaxf(mx, __shfl_xor_sync(0xffffffffu, mx, s));
        float sum = 0.f;
#pragma unroll
        for (int j = 0; j < 16; j++) {
            int r = lane + 32 * j;
            float e = (msk[r] != 0) ? __expf(vals[j] - mx) : 0.f;
            sum += e;
            qk[h * QKS + r] = e;
        }
#pragma unroll
        for (int s = 16; s; s >>= 1) sum += __shfl_xor_sync(0xffffffffu, sum, s);
        if (lane == 0) sinv[h] = 1.f / sum;
    }
    __syncthreads();

    // transposed write: out[r*6144 + c*8 + h] (32B contiguous per r)
#pragma unroll
    for (int k = 0; k < 16; k++) {
        int idx = tid + 256 * k;          // 512 r x 8 h
        int r = idx >> 3, h = idx & 7;
        out[(size_t)r * (C_DIM * H_DIM) + c * H_DIM + h] =
            qk[h * QKS + r] * sinv[h];
    }
}

// ---------------------------------------------------------------------------
extern "C" void kernel_launch(void* const* d_in, const int* in_sizes, int n_in,
                              void* d_out, int out_size) {
    const float* msa  = (const float*)d_in[0];
    const int*   mask = (const int*)d_in[1];
    const float* wq   = (const float*)d_in[2];
    const float* wk   = (const float*)d_in[3];
    float* out = (float*)d_out;

    const int smemQP = (3 * 256 + 3 * 256 + 8192 + 3 * 2048) * 4;  // 63,488
    const int smemMain = (3 * TILE_F + 8 * QKS + 1024 + 512 + 8) * 4; // 72,608
    cudaFuncSetAttribute(kQP,   cudaFuncAttributeMaxDynamicSharedMemorySize, smemQP);
    cudaFuncSetAttribute(kMain, cudaFuncAttributeMaxDynamicSharedMemorySize, smemMain);

    kQP<<<256, 256, smemQP>>>(msa, wq, wk);
    kMain<<<768, 256, smemMain>>>(msa, mask, out);
}